// round 12
// baseline (speedup 1.0000x reference)
#include <cuda_runtime.h>
#include <cuda_bf16.h>
#include <cstdint>
#include <math.h>

#define Bb 2
#define Nn 512
#define Cc 128
#define Hh 8
#define NN (Nn*Nn)

// ---------------------------------------------------------------------------
// Scratch (no cudaMalloc): __device__ globals, all plain fp32 (tf32-rounded).
// g_P: 4 tensors x 16 planes (b*8+h) x [512][512]:
//   tensor 0 = V_in [i][k], 1 = V_out [k][j], 2 = E_in [i][k], 3 = E_out [k][i]
// g_PT: transposed out-planes: z<16 EoutT [i][k], z>=16 VoutT [j][k]
// ---------------------------------------------------------------------------
__device__ float    g_P [4*16*NN];
__device__ float    g_PT[32*NN];
__device__ float    g_Va[32*NN];        // [b][16 s][i][j], s: 0-7 in, 8-15 out
__device__ float    g_WtVE[64*128];     // [n][k] tf32
__device__ float    g_WoT [256*16];     // [n][s] tf32

__device__ __forceinline__ float sigmoidf_(float x){ return 1.0f/(1.0f + __expf(-x)); }

__device__ __forceinline__ uint32_t smem_u32(const void* p) {
    uint32_t a;
    asm("{ .reg .u64 t; cvta.to.shared.u64 t, %1; cvt.u32.u64 %0, t; }" : "=r"(a) : "l"(p));
    return a;
}
__device__ __forceinline__ float f2tf32(float f) {
    uint32_t r;
    asm("cvt.rna.tf32.f32 %0, %1;" : "=r"(r) : "f"(f));
    return __uint_as_float(r);
}
__device__ __forceinline__ void mma_tf32(float* c, const uint32_t* a, const uint32_t* b) {
    asm volatile("mma.sync.aligned.m16n8k8.row.col.f32.tf32.tf32.f32 "
        "{%0,%1,%2,%3}, {%4,%5,%6,%7}, {%8,%9}, {%0,%1,%2,%3};"
        : "+f"(c[0]), "+f"(c[1]), "+f"(c[2]), "+f"(c[3])
        : "r"(a[0]), "r"(a[1]), "r"(a[2]), "r"(a[3]), "r"(b[0]), "r"(b[1]));
}
__device__ __forceinline__ void cpasync16(uint32_t dst, const void* src) {
    asm volatile("cp.async.cg.shared.global [%0], [%1], 16;" :: "r"(dst), "l"(src));
}
#define CP_COMMIT() asm volatile("cp.async.commit_group;" ::: "memory")
#define CP_WAIT0()  asm volatile("cp.async.wait_group 0;" ::: "memory")
#define CP_WAIT1()  asm volatile("cp.async.wait_group 1;" ::: "memory")

// ---------------------------------------------------------------------------
// K0: weight prep (one block).
// ---------------------------------------------------------------------------
__global__ void k0_prep(const float* __restrict__ Wv, const float* __restrict__ We,
                        const float* __restrict__ Wo)
{
    const int t = threadIdx.x;
    for (int idx = t; idx < 8192; idx += 256) {
        int k = idx >> 6, n = idx & 63;
        float w = (n < 32) ? Wv[k*32 + n] : We[k*32 + (n - 32)];
        g_WtVE[n*128 + k] = f2tf32(w);
    }
    for (int idx = t; idx < 4096; idx += 256) {
        int s = idx >> 8, n = idx & 255;
        g_WoT[n*16 + s] = f2tf32(Wo[s*256 + n]);
    }
}

// ---------------------------------------------------------------------------
// K1: LN + dual projection (tf32 MMA, M=128 N=64 K=128) + gating.
// cp.async e-tile staging; sOut padded to stride 132 (bank-conflict-free).
// ---------------------------------------------------------------------------
#define K1_OFF_E    0             // 128*132*4 = 67584
#define K1_OFF_W    67584         // 64*132*4  = 33792 (reused as sOut: 32*132)
#define K1_OFF_BIAS 101376
#define K1_OFF_MASK 101632
#define K1_OFF_PS   102144
#define K1_OFF_PQ   103168
#define K1_OFF_MU   104192
#define K1_OFF_RS   104704
#define K1_OFF_LNW  105216
#define K1_OFF_LNB  105728
#define K1_SMEM     106240

__global__ __launch_bounds__(256) void k1_ln_proj_gate(
    const float* __restrict__ e,
    const float* __restrict__ mask,
    const float* __restrict__ ln_w,
    const float* __restrict__ ln_b,
    const float* __restrict__ bv,
    const float* __restrict__ be)
{
    extern __shared__ char smraw[];
    float* sE    = (float*)(smraw + K1_OFF_E);     // [128][132]
    float* sW    = (float*)(smraw + K1_OFF_W);     // [64][132]
    float* sBias = (float*)(smraw + K1_OFF_BIAS);
    float* sMask = (float*)(smraw + K1_OFF_MASK);
    float* sPs   = (float*)(smraw + K1_OFF_PS);
    float* sPq   = (float*)(smraw + K1_OFF_PQ);
    float* sMu   = (float*)(smraw + K1_OFF_MU);
    float* sRs   = (float*)(smraw + K1_OFF_RS);
    float* sLnW  = (float*)(smraw + K1_OFF_LNW);
    float* sLnB  = (float*)(smraw + K1_OFF_LNB);

    const int t   = threadIdx.x;
    const int wid = t >> 5, lid = t & 31;
    const long g0 = (long)blockIdx.x * 128;
    const int b  = (int)(blockIdx.x >> 11);
    const int x  = (int)((blockIdx.x >> 2) & 511);
    const int y0 = (int)((blockIdx.x & 3) * 128);

    const uint32_t sbE = smem_u32(sE);

    // Kick off e-tile staging with cp.async (MLP ~16 per thread).
    #pragma unroll
    for (int it = 0; it < 16; it++) {
        int idx = it*256 + t;
        int row = idx >> 5, c4 = idx & 31;
        cpasync16(sbE + (uint32_t)((row*132 + c4*4)*4),
                  e + (g0 + row)*Cc + c4*4);
    }
    CP_COMMIT();

    // Overlap: stage weights/params while e streams in.
    for (int idx = t; idx < 8192; idx += 256) {
        int n = idx >> 7, k = idx & 127;
        sW[n*132 + k] = g_WtVE[idx];
    }
    if (t < 64)  sBias[t] = (t < 32) ? bv[t] : be[t - 32];
    if (t < 128) { sLnW[t] = ln_w[t]; sLnB[t] = ln_b[t]; sMask[t] = mask[g0 + t]; }

    CP_WAIT0();
    __syncthreads();

    // LN stats: 2 threads per row.
    {
        int row = t >> 1, half = t & 1;
        float s = 0.f, q = 0.f;
        const float* p = sE + row*132 + half*64;
        #pragma unroll 8
        for (int c = 0; c < 64; c++) { float v = p[c]; s += v; q += v*v; }
        sPs[t] = s; sPq[t] = q;
    }
    __syncthreads();
    if (t < 128) {
        float s = sPs[t*2] + sPs[t*2+1];
        float q = sPq[t*2] + sPq[t*2+1];
        float mu  = s * (1.f/128.f);
        float var = q * (1.f/128.f) - mu*mu;
        sMu[t] = mu;
        sRs[t] = rsqrtf(var + 1e-5f);
    }
    __syncthreads();

    // Normalize + tf32-round in place.
    {
        int row = t >> 1, half = t & 1;
        float mu = sMu[row], rs = sRs[row];
        #pragma unroll 4
        for (int c = half*64; c < half*64 + 64; c++) {
            float v = (sE[row*132 + c] - mu) * rs * sLnW[c] + sLnB[c];
            sE[row*132 + c] = f2tf32(v);
        }
    }
    __syncthreads();

    // MMA: warp wid rows 16*wid..+15; N=64 (8 nt); K=128 (16 k-steps).
    const uint32_t* uE = (const uint32_t*)sE;
    const uint32_t* uW = (const uint32_t*)sW;
    const int r0 = wid*16 + (lid >> 2);
    const int kc = lid & 3;

    float acc[8][4];
    #pragma unroll
    for (int nt = 0; nt < 8; nt++)
        #pragma unroll
        for (int q = 0; q < 4; q++) acc[nt][q] = 0.f;

    #pragma unroll
    for (int ks = 0; ks < 16; ks++) {
        uint32_t a[4];
        a[0] = uE[(r0    )*132 + ks*8 + kc];
        a[1] = uE[(r0 + 8)*132 + ks*8 + kc];
        a[2] = uE[(r0    )*132 + ks*8 + kc + 4];
        a[3] = uE[(r0 + 8)*132 + ks*8 + kc + 4];
        #pragma unroll
        for (int nt = 0; nt < 8; nt++) {
            uint32_t bfr[2];
            int n0 = nt*8 + (lid >> 2);
            bfr[0] = uW[n0*132 + ks*8 + kc];
            bfr[1] = uW[n0*132 + ks*8 + kc + 4];
            mma_tf32(acc[nt], a, bfr);
        }
    }
    __syncthreads();   // all warps done with sW; reuse as sOut [32][132]

    float* sOut = sW;
    #pragma unroll
    for (int q = 0; q < 4; q++) {
        int row = 16*wid + (lid >> 2) + ((q >> 1) * 8);
        int h   = (lid & 3)*2 + (q & 1);
        float m = sMask[row];
        float vin  = sigmoidf_(acc[0][q] + sBias[h]      + m) * (acc[1][q] + sBias[8  + h]);
        float vout = sigmoidf_(acc[2][q] + sBias[16 + h] + m) * (acc[3][q] + sBias[24 + h]);
        float ein  = sigmoidf_(acc[4][q] + sBias[32 + h] + m) * (acc[5][q] + sBias[40 + h]);
        float eout = sigmoidf_(acc[6][q] + sBias[48 + h] + m) * (acc[7][q] + sBias[56 + h]);
        sOut[(0*8 + h)*132 + row] = f2tf32(vin);
        sOut[(1*8 + h)*132 + row] = f2tf32(vout);
        sOut[(2*8 + h)*132 + row] = f2tf32(ein);
        sOut[(3*8 + h)*132 + row] = f2tf32(eout);
    }
    __syncthreads();

    // Coalesced copy out: 32 segments of 128 floats; 8 threads per segment.
    {
        int seg = t >> 3;             // tensor*8 + h
        int sub = t & 7;
        int tensor = seg >> 3, h = seg & 7;
        float* dst = g_P + ((long)(tensor*16 + b*8 + h)*NN) + (long)x*Nn + y0 + sub*16;
        const float* src = sOut + seg*132 + sub*16;
        #pragma unroll
        for (int q = 0; q < 4; q++)
            *(float4*)(dst + q*4) = *(const float4*)(src + q*4);
    }
}

// ---------------------------------------------------------------------------
// Transpose 512x512 fp32 planes: Eout (tensor 3) and Vout (tensor 1) -> g_PT.
// ---------------------------------------------------------------------------
__global__ __launch_bounds__(256) void k_transpose()
{
    __shared__ float tl[32][33];
    const int z = blockIdx.z;
    const float* src = (z < 16) ? (g_P + (long)(3*16 + z)*NN)
                                : (g_P + (long)(1*16 + (z-16))*NN);
    float* dst = g_PT + (long)z*NN;
    const int x0 = blockIdx.x * 32;
    const int y0 = blockIdx.y * 32;
    const int tx = threadIdx.x, ty = threadIdx.y;
    #pragma unroll
    for (int rr = 0; rr < 32; rr += 8)
        tl[ty + rr][tx] = src[(long)(x0 + ty + rr)*Nn + y0 + tx];
    __syncthreads();
    #pragma unroll
    for (int rr = 0; rr < 32; rr += 8)
        dst[(long)(y0 + ty + rr)*Nn + x0 + tx] = tl[tx][ty + rr];
}

// ---------------------------------------------------------------------------
// K2: tf32 GEMM, CTA tile 128x128, K-chunk 32, cp.async double-buffered.
// smem 73.7KB -> 2 CTA/SM. 8 warps = 2(m) x 4(n), warp tile 64x32.
// ---------------------------------------------------------------------------
#define K2_STRF  36
#define K2_TILEF (128*K2_STRF)
#define K2_BUFF  (2*K2_TILEF)
#define K2_SMEMB (2*K2_BUFF*4)   // 73728 B

__global__ __launch_bounds__(256, 2) void k2_mma(float* __restrict__ Va)
{
    extern __shared__ float sm2[];
    const uint32_t sb2 = smem_u32(sm2);
    const int t = threadIdx.x;
    const int wid = t >> 5, lid = t & 31;
    const int warp_m = wid >> 2;
    const int warp_n = wid & 3;

    const int z = blockIdx.z;
    const float* A;
    const float* B;
    float* C;
    if (z < 16) {
        A = g_P + (long)(2*16 + z)*NN;      // E_in [i][k]
        B = g_P + (long)z*NN;               // V_in [j][k]
        C = Va + (long)((z >> 3)*16 + (z & 7))*NN;
    } else {
        int p = z - 16;
        A = g_PT + (long)p*NN;              // EoutT [i][k]
        B = g_PT + (long)(16 + p)*NN;       // VoutT [j][k]
        C = Va + (long)((p >> 3)*16 + 8 + (p & 7))*NN;
    }
    const int i0 = blockIdx.y * 128;
    const int j0 = blockIdx.x * 128;

    const int r0k = lid >> 2;
    const int kc4 = lid & 3;

    float acc[4][4][4];
    #pragma unroll
    for (int mt = 0; mt < 4; mt++)
        #pragma unroll
        for (int nt = 0; nt < 4; nt++)
            #pragma unroll
            for (int q = 0; q < 4; q++) acc[mt][nt][q] = 0.f;

    // Stage K-chunk kc (32 floats wide) into buffer buf: 8 cp.async per thread.
    #define K2_STAGE(kc, buf) do { \
        int _k0 = (kc) * 32; \
        _Pragma("unroll") \
        for (int it = 0; it < 8; it++) { \
            int idx = it*256 + t; \
            int half = idx >> 10; \
            int r = (idx >> 3) & 127; \
            int c = idx & 7; \
            const float* src = (half ? B + (long)(j0 + r)*Nn : A + (long)(i0 + r)*Nn) + _k0 + c*4; \
            uint32_t dst = sb2 + (uint32_t)(((buf)*K2_BUFF + half*K2_TILEF + r*K2_STRF + c*4)*4); \
            cpasync16(dst, src); \
        } \
        CP_COMMIT(); \
    } while (0)

    K2_STAGE(0, 0);

    for (int kc = 0; kc < 16; kc++) {
        if (kc < 15) { K2_STAGE(kc + 1, (kc + 1) & 1); CP_WAIT1(); }
        else         { CP_WAIT0(); }
        __syncthreads();

        const uint32_t* uA = (const uint32_t*)(sm2 + (kc & 1)*K2_BUFF);
        const uint32_t* uB = uA + K2_TILEF;

        #pragma unroll
        for (int ks = 0; ks < 4; ks++) {
            uint32_t a[4][4];
            #pragma unroll
            for (int mt = 0; mt < 4; mt++) {
                int r0 = warp_m*64 + mt*16 + r0k;
                a[mt][0] = uA[(r0    )*K2_STRF + ks*8 + kc4];
                a[mt][1] = uA[(r0 + 8)*K2_STRF + ks*8 + kc4];
                a[mt][2] = uA[(r0    )*K2_STRF + ks*8 + kc4 + 4];
                a[mt][3] = uA[(r0 + 8)*K2_STRF + ks*8 + kc4 + 4];
            }
            #pragma unroll
            for (int nt = 0; nt < 4; nt++) {
                uint32_t bfr[2];
                int n0 = warp_n*32 + nt*8 + r0k;
                bfr[0] = uB[n0*K2_STRF + ks*8 + kc4];
                bfr[1] = uB[n0*K2_STRF + ks*8 + kc4 + 4];
                #pragma unroll
                for (int mt = 0; mt < 4; mt++)
                    mma_tf32(acc[mt][nt], a[mt], bfr);
            }
        }
        __syncthreads();
    }

    const int rbase = i0 + warp_m*64 + (lid >> 2);
    const int cbase = j0 + warp_n*32 + (lid & 3)*2;
    #pragma unroll
    for (int mt = 0; mt < 4; mt++)
        #pragma unroll
        for (int nt = 0; nt < 4; nt++) {
            int row = rbase + mt*16;
            int col = cbase + nt*8;
            *(float2*)(C + (long)row*Nn + col)     = make_float2(acc[mt][nt][0], acc[mt][nt][1]);
            *(float2*)(C + (long)(row+8)*Nn + col) = make_float2(acc[mt][nt][2], acc[mt][nt][3]);
        }
}

// ---------------------------------------------------------------------------
// K3: O = Va @ Wo + bo ; out = sigmoid(O[:128]) * O[128:].
// ---------------------------------------------------------------------------
#define K3_OFF_VA 0              // 512*20*4 = 40960
#define K3_OFF_WO 40960          // 256*20*4 = 20480
#define K3_OFF_BO 61440
#define K3_SMEM   62464

__global__ __launch_bounds__(256, 2) void k3_outproj(
    const float* __restrict__ bo,
    float* __restrict__ out)
{
    extern __shared__ char smraw[];
    float* sVa = (float*)(smraw + K3_OFF_VA);   // [512][20]
    float* sWo = (float*)(smraw + K3_OFF_WO);   // [256][20]
    float* sBo = (float*)(smraw + K3_OFF_BO);

    const int t   = threadIdx.x;
    const int wid = t >> 5, lid = t & 31;
    const int i = blockIdx.x;
    const int b = blockIdx.y;

    if (t < 256) sBo[t] = bo[t];
    for (int idx = t; idx < 4096; idx += 256) {
        int n = idx >> 4, s = idx & 15;
        sWo[n*20 + s] = g_WoT[idx];
    }
    for (int it = 0; it < 32; it++) {
        int idx = it*256 + t;
        int s = idx >> 9, j = idx & 511;
        sVa[j*20 + s] = f2tf32(g_Va[(long)(b*16 + s)*NN + (long)i*Nn + j]);
    }
    __syncthreads();

    const uint32_t* uVa = (const uint32_t*)sVa;
    const uint32_t* uWo = (const uint32_t*)sWo;
    const int rk = lid >> 2;
    const int kc = lid & 3;

    uint32_t a[4][2][4];
    #pragma unroll
    for (int mt = 0; mt < 4; mt++) {
        int r0 = wid*64 + mt*16 + rk;
        #pragma unroll
        for (int ks = 0; ks < 2; ks++) {
            a[mt][ks][0] = uVa[(r0    )*20 + ks*8 + kc];
            a[mt][ks][1] = uVa[(r0 + 8)*20 + ks*8 + kc];
            a[mt][ks][2] = uVa[(r0    )*20 + ks*8 + kc + 4];
            a[mt][ks][3] = uVa[(r0 + 8)*20 + ks*8 + kc + 4];
        }
    }

    float* obase = out + ((long)(b*Nn + i)*Nn) * 128;

    #pragma unroll 4
    for (int cg = 0; cg < 16; cg++) {
        uint32_t bg[2][2], bl[2][2];
        #pragma unroll
        for (int ks = 0; ks < 2; ks++) {
            int ng = cg*8 + rk;
            bg[ks][0] = uWo[(ng      )*20 + ks*8 + kc];
            bg[ks][1] = uWo[(ng      )*20 + ks*8 + kc + 4];
            bl[ks][0] = uWo[(ng + 128)*20 + ks*8 + kc];
            bl[ks][1] = uWo[(ng + 128)*20 + ks*8 + kc + 4];
        }
        float ag[4][4], al[4][4];
        #pragma unroll
        for (int mt = 0; mt < 4; mt++)
            #pragma unroll
            for (int q = 0; q < 4; q++) { ag[mt][q] = 0.f; al[mt][q] = 0.f; }
        #pragma unroll
        for (int ks = 0; ks < 2; ks++)
            #pragma unroll
            for (int mt = 0; mt < 4; mt++) {
                mma_tf32(ag[mt], a[mt][ks], bg[ks]);
                mma_tf32(al[mt], a[mt][ks], bl[ks]);
            }
        int c0 = cg*8 + (lid & 3)*2;
        float bg0 = sBo[c0], bg1 = sBo[c0+1], bl0 = sBo[c0+128], bl1 = sBo[c0+129];
        #pragma unroll
        for (int mt = 0; mt < 4; mt++) {
            int r = wid*64 + mt*16 + (lid >> 2);
            *(float2*)(obase + (long)r*128 + c0) = make_float2(
                sigmoidf_(ag[mt][0] + bg0) * (al[mt][0] + bl0),
                sigmoidf_(ag[mt][1] + bg1) * (al[mt][1] + bl1));
            *(float2*)(obase + (long)(r+8)*128 + c0) = make_float2(
                sigmoidf_(ag[mt][2] + bg0) * (al[mt][2] + bl0),
                sigmoidf_(ag[mt][3] + bg1) * (al[mt][3] + bl1));
        }
    }
}

// ---------------------------------------------------------------------------
extern "C" void kernel_launch(void* const* d_in, const int* in_sizes, int n_in,
                              void* d_out, int out_size)
{
    const float* e    = (const float*)d_in[0];
    const float* mask = (const float*)d_in[1];
    const float* lnw  = (const float*)d_in[2];
    const float* lnb  = (const float*)d_in[3];
    const float* Wv   = (const float*)d_in[4];
    const float* bv   = (const float*)d_in[5];
    const float* We   = (const float*)d_in[6];
    const float* be   = (const float*)d_in[7];
    const float* Wo   = (const float*)d_in[8];
    const float* bo   = (const float*)d_in[9];
    float* out = (float*)d_out;

    static float* s_va = nullptr;
    if (!s_va) cudaGetSymbolAddress((void**)&s_va, g_Va);

    cudaFuncSetAttribute(k1_ln_proj_gate,
                         cudaFuncAttributeMaxDynamicSharedMemorySize, K1_SMEM);
    cudaFuncSetAttribute(k2_mma,
                         cudaFuncAttributeMaxDynamicSharedMemorySize, K2_SMEMB);
    cudaFuncSetAttribute(k3_outproj,
                         cudaFuncAttributeMaxDynamicSharedMemorySize, K3_SMEM);

    k0_prep<<<1, 256>>>(Wv, We, Wo);

    k1_ln_proj_gate<<<4096, 256, K1_SMEM>>>(e, mask, lnw, lnb, bv, be);

    dim3 gt(16, 16, 32);
    k_transpose<<<gt, dim3(32, 8)>>>();

    dim3 g2(4, 4, 32);
    k2_mma<<<g2, 256, K2_SMEMB>>>(s_va);

    dim3 g3(Nn, Bb);
    k3_outproj<<<g3, 256, K3_SMEM>>>(bo, out);
}

// round 14
// speedup vs baseline: 1.0154x; 1.0154x over previous
#include <cuda_runtime.h>
#include <cuda_bf16.h>
#include <cstdint>
#include <math.h>

#define Bb 2
#define Nn 512
#define Cc 128
#define Hh 8
#define NN (Nn*Nn)

// ---------------------------------------------------------------------------
// Scratch: __device__ globals, all plain fp32 (tf32-rounded).
// g_P: 4 tensors x 16 planes (b*8+h) x [512][512]:
//   tensor 0 = V_in [i][k], 1 = V_out [k][j], 2 = E_in [i][k], 3 = E_out [k][i]
// ---------------------------------------------------------------------------
__device__ float    g_P [4*16*NN];
__device__ float    g_Va[32*NN];        // [b][16 s][i][j], s: 0-7 in, 8-15 out
__device__ float    g_WtVE[64*128];     // [n][k] tf32
__device__ float    g_WoT [256*16];     // [n][s] tf32

__device__ __forceinline__ float sigmoidf_(float x){ return 1.0f/(1.0f + __expf(-x)); }

__device__ __forceinline__ uint32_t smem_u32(const void* p) {
    uint32_t a;
    asm("{ .reg .u64 t; cvta.to.shared.u64 t, %1; cvt.u32.u64 %0, t; }" : "=r"(a) : "l"(p));
    return a;
}
__device__ __forceinline__ float f2tf32(float f) {
    uint32_t r;
    asm("cvt.rna.tf32.f32 %0, %1;" : "=r"(r) : "f"(f));
    return __uint_as_float(r);
}
__device__ __forceinline__ void mma_tf32(float* c, const uint32_t* a, const uint32_t* b) {
    asm volatile("mma.sync.aligned.m16n8k8.row.col.f32.tf32.tf32.f32 "
        "{%0,%1,%2,%3}, {%4,%5,%6,%7}, {%8,%9}, {%0,%1,%2,%3};"
        : "+f"(c[0]), "+f"(c[1]), "+f"(c[2]), "+f"(c[3])
        : "r"(a[0]), "r"(a[1]), "r"(a[2]), "r"(a[3]), "r"(b[0]), "r"(b[1]));
}
__device__ __forceinline__ void cpasync16(uint32_t dst, const void* src) {
    asm volatile("cp.async.cg.shared.global [%0], [%1], 16;" :: "r"(dst), "l"(src));
}
#define CP_COMMIT() asm volatile("cp.async.commit_group;" ::: "memory")
#define CP_WAIT0()  asm volatile("cp.async.wait_group 0;" ::: "memory")
#define CP_WAIT1()  asm volatile("cp.async.wait_group 1;" ::: "memory")

// ---------------------------------------------------------------------------
// K0: weight prep (one block).
// ---------------------------------------------------------------------------
__global__ void k0_prep(const float* __restrict__ Wv, const float* __restrict__ We,
                        const float* __restrict__ Wo)
{
    const int t = threadIdx.x;
    for (int idx = t; idx < 8192; idx += 256) {
        int k = idx >> 6, n = idx & 63;
        float w = (n < 32) ? Wv[k*32 + n] : We[k*32 + (n - 32)];
        g_WtVE[n*128 + k] = f2tf32(w);
    }
    for (int idx = t; idx < 4096; idx += 256) {
        int s = idx >> 8, n = idx & 255;
        g_WoT[n*16 + s] = f2tf32(Wo[s*256 + n]);
    }
}

// ---------------------------------------------------------------------------
// K1 (persistent): LN + dual projection (tf32 MMA) + gating.
// grid = #SMs; each CTA loops over 128-row tiles, double-buffering the e-tile
// via cp.async so DRAM reads overlap compute. Weights staged once.
// ---------------------------------------------------------------------------
#define K1_OFF_E     0              // 2 x 128*132*4 = 135168
#define K1_OFF_W     135168         // 64*132*4 = 33792
#define K1_OFF_BIAS  168960         // 256
#define K1_OFF_MASK  169216         // 2 x 128*4 = 1024
#define K1_OFF_PS    170240         // 1024
#define K1_OFF_PQ    171264         // 1024
#define K1_OFF_MU    172288         // 512
#define K1_OFF_RS    172800         // 512
#define K1_OFF_LNW   173312         // 512
#define K1_OFF_LNB   173824         // 512
#define K1_OFF_OUT   174336         // 32*132*4 = 16896 (gate-staging)
#define K1_SMEM      191232
#define K1_EBUF      (128*132)      // floats per e buffer

__global__ __launch_bounds__(256) void k1_ln_proj_gate(
    const float* __restrict__ e,
    const float* __restrict__ mask,
    const float* __restrict__ ln_w,
    const float* __restrict__ ln_b,
    const float* __restrict__ bv,
    const float* __restrict__ be)
{
    extern __shared__ char smraw[];
    float* sEb   = (float*)(smraw + K1_OFF_E);      // [2][128][132]
    float* sW    = (float*)(smraw + K1_OFF_W);      // [64][132]
    float* sBias = (float*)(smraw + K1_OFF_BIAS);
    float* sMaskb= (float*)(smraw + K1_OFF_MASK);   // [2][128]
    float* sPs   = (float*)(smraw + K1_OFF_PS);
    float* sPq   = (float*)(smraw + K1_OFF_PQ);
    float* sMu   = (float*)(smraw + K1_OFF_MU);
    float* sRs   = (float*)(smraw + K1_OFF_RS);
    float* sLnW  = (float*)(smraw + K1_OFF_LNW);
    float* sLnB  = (float*)(smraw + K1_OFF_LNB);
    float* sOut  = (float*)(smraw + K1_OFF_OUT);    // [32][132]

    const int t   = threadIdx.x;
    const int wid = t >> 5, lid = t & 31;
    const uint32_t sbE = smem_u32(sEb);
    const uint32_t sbM = smem_u32(sMaskb);
    const int G = gridDim.x;

    // One-time staging: weights + LN params + biases.
    for (int idx = t; idx < 8192; idx += 256) {
        int n = idx >> 7, k = idx & 127;
        sW[n*132 + k] = g_WtVE[idx];
    }
    if (t < 64)  sBias[t] = (t < 32) ? bv[t] : be[t - 32];
    if (t < 128) { sLnW[t] = ln_w[t]; sLnB[t] = ln_b[t]; }

    // Prefetch first tile into buffer 0.
    {
        long g0 = (long)blockIdx.x * 128;
        #pragma unroll
        for (int it = 0; it < 16; it++) {
            int idx = it*256 + t;
            int row = idx >> 5, c4 = idx & 31;
            cpasync16(sbE + (uint32_t)((row*132 + c4*4)*4), e + (g0 + row)*Cc + c4*4);
        }
        if (t < 32) cpasync16(sbM + t*16, mask + g0 + t*4);
        CP_COMMIT();
    }

    int buf = 0;
    for (int tidx = blockIdx.x; tidx < 4096; tidx += G, buf ^= 1) {
        const long g0 = (long)tidx * 128;
        const int b  = tidx >> 11;
        const int x  = (tidx >> 2) & 511;
        const int y0 = (tidx & 3) * 128;
        float* sE    = sEb + buf*K1_EBUF;
        float* sMask = sMaskb + buf*128;

        CP_WAIT0();
        __syncthreads();

        // Prefetch next tile into the other buffer (its last reader finished
        // at the end-sync of the previous iteration).
        {
            int nidx = tidx + G;
            if (nidx < 4096) {
                long ng0 = (long)nidx * 128;
                uint32_t dstE = sbE + (uint32_t)((buf ^ 1) * K1_EBUF * 4);
                #pragma unroll
                for (int it = 0; it < 16; it++) {
                    int idx = it*256 + t;
                    int row = idx >> 5, c4 = idx & 31;
                    cpasync16(dstE + (uint32_t)((row*132 + c4*4)*4),
                              e + (ng0 + row)*Cc + c4*4);
                }
                if (t < 32) cpasync16(sbM + (uint32_t)((buf ^ 1)*128*4) + t*16,
                                      mask + ng0 + t*4);
                CP_COMMIT();
            }
        }

        // LN stats: 2 threads per row.
        {
            int row = t >> 1, half = t & 1;
            float s = 0.f, q = 0.f;
            const float* p = sE + row*132 + half*64;
            #pragma unroll 8
            for (int c = 0; c < 64; c++) { float v = p[c]; s += v; q += v*v; }
            sPs[t] = s; sPq[t] = q;
        }
        __syncthreads();
        if (t < 128) {
            float s = sPs[t*2] + sPs[t*2+1];
            float q = sPq[t*2] + sPq[t*2+1];
            float mu  = s * (1.f/128.f);
            float var = q * (1.f/128.f) - mu*mu;
            sMu[t] = mu;
            sRs[t] = rsqrtf(var + 1e-5f);
        }
        __syncthreads();

        // Normalize + tf32-round in place.
        {
            int row = t >> 1, half = t & 1;
            float mu = sMu[row], rs = sRs[row];
            #pragma unroll 4
            for (int c = half*64; c < half*64 + 64; c++) {
                float v = (sE[row*132 + c] - mu) * rs * sLnW[c] + sLnB[c];
                sE[row*132 + c] = f2tf32(v);
            }
        }
        __syncthreads();

        // MMA: warp wid rows 16*wid..+15; N=64 (8 nt); K=128 (16 k-steps).
        const uint32_t* uE = (const uint32_t*)sE;
        const uint32_t* uW = (const uint32_t*)sW;
        const int r0 = wid*16 + (lid >> 2);
        const int kc = lid & 3;

        float acc[8][4];
        #pragma unroll
        for (int nt = 0; nt < 8; nt++)
            #pragma unroll
            for (int q = 0; q < 4; q++) acc[nt][q] = 0.f;

        #pragma unroll
        for (int ks = 0; ks < 16; ks++) {
            uint32_t a[4];
            a[0] = uE[(r0    )*132 + ks*8 + kc];
            a[1] = uE[(r0 + 8)*132 + ks*8 + kc];
            a[2] = uE[(r0    )*132 + ks*8 + kc + 4];
            a[3] = uE[(r0 + 8)*132 + ks*8 + kc + 4];
            #pragma unroll
            for (int nt = 0; nt < 8; nt++) {
                uint32_t bfr[2];
                int n0 = nt*8 + (lid >> 2);
                bfr[0] = uW[n0*132 + ks*8 + kc];
                bfr[1] = uW[n0*132 + ks*8 + kc + 4];
                mma_tf32(acc[nt], a, bfr);
            }
        }

        // Gate -> sOut[tensor*8+h][row] then coalesced copy to planes.
        #pragma unroll
        for (int q = 0; q < 4; q++) {
            int row = 16*wid + (lid >> 2) + ((q >> 1) * 8);
            int h   = (lid & 3)*2 + (q & 1);
            float m = sMask[row];
            float vin  = sigmoidf_(acc[0][q] + sBias[h]      + m) * (acc[1][q] + sBias[8  + h]);
            float vout = sigmoidf_(acc[2][q] + sBias[16 + h] + m) * (acc[3][q] + sBias[24 + h]);
            float ein  = sigmoidf_(acc[4][q] + sBias[32 + h] + m) * (acc[5][q] + sBias[40 + h]);
            float eout = sigmoidf_(acc[6][q] + sBias[48 + h] + m) * (acc[7][q] + sBias[56 + h]);
            sOut[(0*8 + h)*132 + row] = f2tf32(vin);
            sOut[(1*8 + h)*132 + row] = f2tf32(vout);
            sOut[(2*8 + h)*132 + row] = f2tf32(ein);
            sOut[(3*8 + h)*132 + row] = f2tf32(eout);
        }
        __syncthreads();

        {
            int seg = t >> 3;             // tensor*8 + h
            int sub = t & 7;
            int tensor = seg >> 3, h = seg & 7;
            float* dst = g_P + ((long)(tensor*16 + b*8 + h)*NN) + (long)x*Nn + y0 + sub*16;
            const float* src = sOut + seg*132 + sub*16;
            #pragma unroll
            for (int q = 0; q < 4; q++)
                *(float4*)(dst + q*4) = *(const float4*)(src + q*4);
        }
        __syncthreads();   // all done with sE/sOut before next iteration reuses
    }
}

// ---------------------------------------------------------------------------
// K2: tf32 GEMM, CTA tile 128x128, K-chunk 32, cp.async double-buffered.
// OUTM=false: A=E_in [i][k], B=V_in [j][k] (row-major i, staged as [i][k]).
// OUTM=true:  A=E_out [k][i], B=V_out [k][j] native k-major; staged as
//             [k][i] tiles (coalesced 512B rows) and fragment-loads index
//             them transposed — NO separate transpose pass.
// ---------------------------------------------------------------------------
#define K2_STRF   36                 // in-mode row stride (floats)
#define K2_STRT   132                // out-mode row stride (floats)
#define K2_TILEF  4608               // floats per tile buffer (max of modes)
#define K2_BUFF   (2*K2_TILEF)
#define K2_SMEMB  (2*K2_BUFF*4)      // 73728 B

template<bool OUTM>
__global__ __launch_bounds__(256, 2) void k2_mma(float* __restrict__ Va)
{
    extern __shared__ float sm2[];
    const uint32_t sb2 = smem_u32(sm2);
    const int t = threadIdx.x;
    const int wid = t >> 5, lid = t & 31;
    const int warp_m = wid >> 2;
    const int warp_n = wid & 3;

    const int z = blockIdx.z;   // plane 0..15
    const float* A;
    const float* B;
    float* C;
    if (!OUTM) {
        A = g_P + (long)(2*16 + z)*NN;      // E_in [i][k]
        B = g_P + (long)z*NN;               // V_in [j][k]
        C = Va + (long)((z >> 3)*16 + (z & 7))*NN;
    } else {
        A = g_P + (long)(3*16 + z)*NN;      // E_out [k][i]
        B = g_P + (long)(1*16 + z)*NN;      // V_out [k][j]
        C = Va + (long)((z >> 3)*16 + 8 + (z & 7))*NN;
    }
    const int i0 = blockIdx.y * 128;
    const int j0 = blockIdx.x * 128;

    const int r0k = lid >> 2;
    const int kc4 = lid & 3;

    float acc[4][4][4];
    #pragma unroll
    for (int mt = 0; mt < 4; mt++)
        #pragma unroll
        for (int nt = 0; nt < 4; nt++)
            #pragma unroll
            for (int q = 0; q < 4; q++) acc[mt][nt][q] = 0.f;

    // Stage chunk kc into buffer buf. 8 cp.async (16B) per thread.
    #define K2_STAGE(kc, buf) do { \
        int _k0 = (kc) * 32; \
        if (!OUTM) { \
            _Pragma("unroll") \
            for (int it = 0; it < 8; it++) { \
                int idx = it*256 + t; \
                int half = idx >> 10; \
                int r = (idx >> 3) & 127; \
                int c = idx & 7; \
                const float* src = (half ? B + (long)(j0 + r)*Nn : A + (long)(i0 + r)*Nn) + _k0 + c*4; \
                uint32_t dst = sb2 + (uint32_t)(((buf)*K2_BUFF + half*K2_TILEF + r*K2_STRF + c*4)*4); \
                cpasync16(dst, src); \
            } \
        } else { \
            _Pragma("unroll") \
            for (int it = 0; it < 8; it++) { \
                int idx = it*256 + t; \
                int half = idx >> 10; \
                int kk = (idx >> 5) & 31; \
                int c = idx & 31; \
                const float* src = (half ? B + (long)(_k0 + kk)*Nn + j0 : A + (long)(_k0 + kk)*Nn + i0) + c*4; \
                uint32_t dst = sb2 + (uint32_t)(((buf)*K2_BUFF + half*K2_TILEF + kk*K2_STRT + c*4)*4); \
                cpasync16(dst, src); \
            } \
        } \
        CP_COMMIT(); \
    } while (0)

    K2_STAGE(0, 0);

    for (int kc = 0; kc < 16; kc++) {
        if (kc < 15) { K2_STAGE(kc + 1, (kc + 1) & 1); CP_WAIT1(); }
        else         { CP_WAIT0(); }
        __syncthreads();

        const uint32_t* uA = (const uint32_t*)(sm2 + (kc & 1)*K2_BUFF);
        const uint32_t* uB = uA + K2_TILEF;

        #pragma unroll
        for (int ks = 0; ks < 4; ks++) {
            uint32_t a[4][4];
            #pragma unroll
            for (int mt = 0; mt < 4; mt++) {
                int r0 = warp_m*64 + mt*16 + r0k;
                if (!OUTM) {
                    a[mt][0] = uA[(r0    )*K2_STRF + ks*8 + kc4];
                    a[mt][1] = uA[(r0 + 8)*K2_STRF + ks*8 + kc4];
                    a[mt][2] = uA[(r0    )*K2_STRF + ks*8 + kc4 + 4];
                    a[mt][3] = uA[(r0 + 8)*K2_STRF + ks*8 + kc4 + 4];
                } else {
                    int kk = ks*8 + kc4;
                    a[mt][0] = uA[(kk    )*K2_STRT + r0    ];
                    a[mt][1] = uA[(kk    )*K2_STRT + r0 + 8];
                    a[mt][2] = uA[(kk + 4)*K2_STRT + r0    ];
                    a[mt][3] = uA[(kk + 4)*K2_STRT + r0 + 8];
                }
            }
            #pragma unroll
            for (int nt = 0; nt < 4; nt++) {
                uint32_t bfr[2];
                int n0 = warp_n*32 + nt*8 + r0k;
                if (!OUTM) {
                    bfr[0] = uB[n0*K2_STRF + ks*8 + kc4];
                    bfr[1] = uB[n0*K2_STRF + ks*8 + kc4 + 4];
                } else {
                    int kk = ks*8 + kc4;
                    bfr[0] = uB[(kk    )*K2_STRT + n0];
                    bfr[1] = uB[(kk + 4)*K2_STRT + n0];
                }
                #pragma unroll
                for (int mt = 0; mt < 4; mt++)
                    mma_tf32(acc[mt][nt], a[mt], bfr);
            }
        }
        __syncthreads();
    }

    const int rbase = i0 + warp_m*64 + (lid >> 2);
    const int cbase = j0 + warp_n*32 + (lid & 3)*2;
    #pragma unroll
    for (int mt = 0; mt < 4; mt++)
        #pragma unroll
        for (int nt = 0; nt < 4; nt++) {
            int row = rbase + mt*16;
            int col = cbase + nt*8;
            *(float2*)(C + (long)row*Nn + col)     = make_float2(acc[mt][nt][0], acc[mt][nt][1]);
            *(float2*)(C + (long)(row+8)*Nn + col) = make_float2(acc[mt][nt][2], acc[mt][nt][3]);
        }
}

// ---------------------------------------------------------------------------
// K3: O = Va @ Wo + bo ; out = sigmoid(O[:128]) * O[128:].
// ---------------------------------------------------------------------------
#define K3_OFF_VA 0              // 512*20*4 = 40960
#define K3_OFF_WO 40960          // 256*20*4 = 20480
#define K3_OFF_BO 61440
#define K3_SMEM   62464

__global__ __launch_bounds__(256, 2) void k3_outproj(
    const float* __restrict__ bo,
    float* __restrict__ out)
{
    extern __shared__ char smraw[];
    float* sVa = (float*)(smraw + K3_OFF_VA);   // [512][20]
    float* sWo = (float*)(smraw + K3_OFF_WO);   // [256][20]
    float* sBo = (float*)(smraw + K3_OFF_BO);

    const int t   = threadIdx.x;
    const int wid = t >> 5, lid = t & 31;
    const int i = blockIdx.x;
    const int b = blockIdx.y;

    if (t < 256) sBo[t] = bo[t];
    for (int idx = t; idx < 4096; idx += 256) {
        int n = idx >> 4, s = idx & 15;
        sWo[n*20 + s] = g_WoT[idx];
    }
    for (int it = 0; it < 32; it++) {
        int idx = it*256 + t;
        int s = idx >> 9, j = idx & 511;
        sVa[j*20 + s] = f2tf32(g_Va[(long)(b*16 + s)*NN + (long)i*Nn + j]);
    }
    __syncthreads();

    const uint32_t* uVa = (const uint32_t*)sVa;
    const uint32_t* uWo = (const uint32_t*)sWo;
    const int rk = lid >> 2;
    const int kc = lid & 3;

    uint32_t a[4][2][4];
    #pragma unroll
    for (int mt = 0; mt < 4; mt++) {
        int r0 = wid*64 + mt*16 + rk;
        #pragma unroll
        for (int ks = 0; ks < 2; ks++) {
            a[mt][ks][0] = uVa[(r0    )*20 + ks*8 + kc];
            a[mt][ks][1] = uVa[(r0 + 8)*20 + ks*8 + kc];
            a[mt][ks][2] = uVa[(r0    )*20 + ks*8 + kc + 4];
            a[mt][ks][3] = uVa[(r0 + 8)*20 + ks*8 + kc + 4];
        }
    }

    float* obase = out + ((long)(b*Nn + i)*Nn) * 128;

    #pragma unroll 4
    for (int cg = 0; cg < 16; cg++) {
        uint32_t bg[2][2], bl[2][2];
        #pragma unroll
        for (int ks = 0; ks < 2; ks++) {
            int ng = cg*8 + rk;
            bg[ks][0] = uWo[(ng      )*20 + ks*8 + kc];
            bg[ks][1] = uWo[(ng      )*20 + ks*8 + kc + 4];
            bl[ks][0] = uWo[(ng + 128)*20 + ks*8 + kc];
            bl[ks][1] = uWo[(ng + 128)*20 + ks*8 + kc + 4];
        }
        float ag[4][4], al[4][4];
        #pragma unroll
        for (int mt = 0; mt < 4; mt++)
            #pragma unroll
            for (int q = 0; q < 4; q++) { ag[mt][q] = 0.f; al[mt][q] = 0.f; }
        #pragma unroll
        for (int ks = 0; ks < 2; ks++)
            #pragma unroll
            for (int mt = 0; mt < 4; mt++) {
                mma_tf32(ag[mt], a[mt][ks], bg[ks]);
                mma_tf32(al[mt], a[mt][ks], bl[ks]);
            }
        int c0 = cg*8 + (lid & 3)*2;
        float bg0 = sBo[c0], bg1 = sBo[c0+1], bl0 = sBo[c0+128], bl1 = sBo[c0+129];
        #pragma unroll
        for (int mt = 0; mt < 4; mt++) {
            int r = wid*64 + mt*16 + (lid >> 2);
            *(float2*)(obase + (long)r*128 + c0) = make_float2(
                sigmoidf_(ag[mt][0] + bg0) * (al[mt][0] + bl0),
                sigmoidf_(ag[mt][1] + bg1) * (al[mt][1] + bl1));
            *(float2*)(obase + (long)(r+8)*128 + c0) = make_float2(
                sigmoidf_(ag[mt][2] + bg0) * (al[mt][2] + bl0),
                sigmoidf_(ag[mt][3] + bg1) * (al[mt][3] + bl1));
        }
    }
}

// ---------------------------------------------------------------------------
extern "C" void kernel_launch(void* const* d_in, const int* in_sizes, int n_in,
                              void* d_out, int out_size)
{
    const float* e    = (const float*)d_in[0];
    const float* mask = (const float*)d_in[1];
    const float* lnw  = (const float*)d_in[2];
    const float* lnb  = (const float*)d_in[3];
    const float* Wv   = (const float*)d_in[4];
    const float* bv   = (const float*)d_in[5];
    const float* We   = (const float*)d_in[6];
    const float* be   = (const float*)d_in[7];
    const float* Wo   = (const float*)d_in[8];
    const float* bo   = (const float*)d_in[9];
    float* out = (float*)d_out;

    static float* s_va = nullptr;
    static int smcount = 0;
    if (!s_va) {
        cudaGetSymbolAddress((void**)&s_va, g_Va);
        cudaDeviceGetAttribute(&smcount, cudaDevAttrMultiProcessorCount, 0);
        if (smcount <= 0) smcount = 148;
        cudaFuncSetAttribute(k1_ln_proj_gate,
                             cudaFuncAttributeMaxDynamicSharedMemorySize, K1_SMEM);
        cudaFuncSetAttribute(k2_mma<false>,
                             cudaFuncAttributeMaxDynamicSharedMemorySize, K2_SMEMB);
        cudaFuncSetAttribute(k2_mma<true>,
                             cudaFuncAttributeMaxDynamicSharedMemorySize, K2_SMEMB);
        cudaFuncSetAttribute(k3_outproj,
                             cudaFuncAttributeMaxDynamicSharedMemorySize, K3_SMEM);
    }

    k0_prep<<<1, 256>>>(Wv, We, Wo);

    k1_ln_proj_gate<<<smcount, 256, K1_SMEM>>>(e, mask, lnw, lnb, bv, be);

    dim3 g2(4, 4, 16);
    k2_mma<false><<<g2, 256, K2_SMEMB>>>(s_va);
    k2_mma<true ><<<g2, 256, K2_SMEMB>>>(s_va);

    dim3 g3(Nn, Bb);
    k3_outproj<<<g3, 256, K3_SMEM>>>(bo, out);
}

// round 15
// speedup vs baseline: 1.0487x; 1.0329x over previous
#include <cuda_runtime.h>
#include <cuda_bf16.h>
#include <cstdint>
#include <math.h>

#define Bb 2
#define Nn 512
#define Cc 128
#define Hh 8
#define NN (Nn*Nn)

// ---------------------------------------------------------------------------
// Scratch: __device__ globals, all plain fp32 (tf32-rounded).
// g_P: 4 tensors x 16 planes (b*8+h) x [512][512]:
//   tensor 0 = V_in [i][k], 1 = V_out [k][j], 2 = E_in [i][k], 3 = E_out [k][i]
// ---------------------------------------------------------------------------
__device__ float    g_P [4*16*NN];
__device__ float    g_Va[32*NN];        // [b][16 s][i][j], s: 0-7 in, 8-15 out
__device__ float    g_WtVE[64*128];     // [n][k] tf32
__device__ float    g_WoT [256*16];     // [n][s] tf32

__device__ __forceinline__ float sigmoidf_(float x){ return 1.0f/(1.0f + __expf(-x)); }

__device__ __forceinline__ uint32_t smem_u32(const void* p) {
    uint32_t a;
    asm("{ .reg .u64 t; cvta.to.shared.u64 t, %1; cvt.u32.u64 %0, t; }" : "=r"(a) : "l"(p));
    return a;
}
__device__ __forceinline__ float f2tf32(float f) {
    uint32_t r;
    asm("cvt.rna.tf32.f32 %0, %1;" : "=r"(r) : "f"(f));
    return __uint_as_float(r);
}
__device__ __forceinline__ void mma_tf32(float* c, const uint32_t* a, const uint32_t* b) {
    asm volatile("mma.sync.aligned.m16n8k8.row.col.f32.tf32.tf32.f32 "
        "{%0,%1,%2,%3}, {%4,%5,%6,%7}, {%8,%9}, {%0,%1,%2,%3};"
        : "+f"(c[0]), "+f"(c[1]), "+f"(c[2]), "+f"(c[3])
        : "r"(a[0]), "r"(a[1]), "r"(a[2]), "r"(a[3]), "r"(b[0]), "r"(b[1]));
}
__device__ __forceinline__ void cpasync16(uint32_t dst, const void* src) {
    asm volatile("cp.async.cg.shared.global [%0], [%1], 16;" :: "r"(dst), "l"(src));
}
#define CP_COMMIT() asm volatile("cp.async.commit_group;" ::: "memory")
#define CP_WAIT0()  asm volatile("cp.async.wait_group 0;" ::: "memory")
#define CP_WAIT1()  asm volatile("cp.async.wait_group 1;" ::: "memory")

// ---------------------------------------------------------------------------
// K0: weight prep (one block).
// ---------------------------------------------------------------------------
__global__ void k0_prep(const float* __restrict__ Wv, const float* __restrict__ We,
                        const float* __restrict__ Wo)
{
    const int t = threadIdx.x;
    for (int idx = t; idx < 8192; idx += 256) {
        int k = idx >> 6, n = idx & 63;
        float w = (n < 32) ? Wv[k*32 + n] : We[k*32 + (n - 32)];
        g_WtVE[n*128 + k] = f2tf32(w);
    }
    for (int idx = t; idx < 4096; idx += 256) {
        int s = idx >> 8, n = idx & 255;
        g_WoT[n*16 + s] = f2tf32(Wo[s*256 + n]);
    }
}

// ---------------------------------------------------------------------------
// K1 (persistent): LN + dual projection (tf32 MMA) + gating.
// ---------------------------------------------------------------------------
#define K1_OFF_E     0              // 2 x 128*132*4 = 135168
#define K1_OFF_W     135168         // 64*132*4 = 33792
#define K1_OFF_BIAS  168960
#define K1_OFF_MASK  169216
#define K1_OFF_PS    170240
#define K1_OFF_PQ    171264
#define K1_OFF_MU    172288
#define K1_OFF_RS    172800
#define K1_OFF_LNW   173312
#define K1_OFF_LNB   173824
#define K1_OFF_OUT   174336         // 32*132*4 = 16896
#define K1_SMEM      191232
#define K1_EBUF      (128*132)

__global__ __launch_bounds__(256) void k1_ln_proj_gate(
    const float* __restrict__ e,
    const float* __restrict__ mask,
    const float* __restrict__ ln_w,
    const float* __restrict__ ln_b,
    const float* __restrict__ bv,
    const float* __restrict__ be)
{
    extern __shared__ char smraw[];
    float* sEb   = (float*)(smraw + K1_OFF_E);
    float* sW    = (float*)(smraw + K1_OFF_W);
    float* sBias = (float*)(smraw + K1_OFF_BIAS);
    float* sMaskb= (float*)(smraw + K1_OFF_MASK);
    float* sPs   = (float*)(smraw + K1_OFF_PS);
    float* sPq   = (float*)(smraw + K1_OFF_PQ);
    float* sMu   = (float*)(smraw + K1_OFF_MU);
    float* sRs   = (float*)(smraw + K1_OFF_RS);
    float* sLnW  = (float*)(smraw + K1_OFF_LNW);
    float* sLnB  = (float*)(smraw + K1_OFF_LNB);
    float* sOut  = (float*)(smraw + K1_OFF_OUT);

    const int t   = threadIdx.x;
    const int wid = t >> 5, lid = t & 31;
    const uint32_t sbE = smem_u32(sEb);
    const uint32_t sbM = smem_u32(sMaskb);
    const int G = gridDim.x;

    for (int idx = t; idx < 8192; idx += 256) {
        int n = idx >> 7, k = idx & 127;
        sW[n*132 + k] = g_WtVE[idx];
    }
    if (t < 64)  sBias[t] = (t < 32) ? bv[t] : be[t - 32];
    if (t < 128) { sLnW[t] = ln_w[t]; sLnB[t] = ln_b[t]; }

    {
        long g0 = (long)blockIdx.x * 128;
        #pragma unroll
        for (int it = 0; it < 16; it++) {
            int idx = it*256 + t;
            int row = idx >> 5, c4 = idx & 31;
            cpasync16(sbE + (uint32_t)((row*132 + c4*4)*4), e + (g0 + row)*Cc + c4*4);
        }
        if (t < 32) cpasync16(sbM + t*16, mask + g0 + t*4);
        CP_COMMIT();
    }

    int buf = 0;
    for (int tidx = blockIdx.x; tidx < 4096; tidx += G, buf ^= 1) {
        const int b  = tidx >> 11;
        const int x  = (tidx >> 2) & 511;
        const int y0 = (tidx & 3) * 128;
        float* sE    = sEb + buf*K1_EBUF;
        float* sMask = sMaskb + buf*128;

        CP_WAIT0();
        __syncthreads();

        {
            int nidx = tidx + G;
            if (nidx < 4096) {
                long ng0 = (long)nidx * 128;
                uint32_t dstE = sbE + (uint32_t)((buf ^ 1) * K1_EBUF * 4);
                #pragma unroll
                for (int it = 0; it < 16; it++) {
                    int idx = it*256 + t;
                    int row = idx >> 5, c4 = idx & 31;
                    cpasync16(dstE + (uint32_t)((row*132 + c4*4)*4),
                              e + (ng0 + row)*Cc + c4*4);
                }
                if (t < 32) cpasync16(sbM + (uint32_t)((buf ^ 1)*128*4) + t*16,
                                      mask + ng0 + t*4);
                CP_COMMIT();
            }
        }

        {
            int row = t >> 1, half = t & 1;
            float s = 0.f, q = 0.f;
            const float* p = sE + row*132 + half*64;
            #pragma unroll 8
            for (int c = 0; c < 64; c++) { float v = p[c]; s += v; q += v*v; }
            sPs[t] = s; sPq[t] = q;
        }
        __syncthreads();
        if (t < 128) {
            float s = sPs[t*2] + sPs[t*2+1];
            float q = sPq[t*2] + sPq[t*2+1];
            float mu  = s * (1.f/128.f);
            float var = q * (1.f/128.f) - mu*mu;
            sMu[t] = mu;
            sRs[t] = rsqrtf(var + 1e-5f);
        }
        __syncthreads();

        {
            int row = t >> 1, half = t & 1;
            float mu = sMu[row], rs = sRs[row];
            #pragma unroll 4
            for (int c = half*64; c < half*64 + 64; c++) {
                float v = (sE[row*132 + c] - mu) * rs * sLnW[c] + sLnB[c];
                sE[row*132 + c] = f2tf32(v);
            }
        }
        __syncthreads();

        const uint32_t* uE = (const uint32_t*)sE;
        const uint32_t* uW = (const uint32_t*)sW;
        const int r0 = wid*16 + (lid >> 2);
        const int kc = lid & 3;

        float acc[8][4];
        #pragma unroll
        for (int nt = 0; nt < 8; nt++)
            #pragma unroll
            for (int q = 0; q < 4; q++) acc[nt][q] = 0.f;

        #pragma unroll
        for (int ks = 0; ks < 16; ks++) {
            uint32_t a[4];
            a[0] = uE[(r0    )*132 + ks*8 + kc];
            a[1] = uE[(r0 + 8)*132 + ks*8 + kc];
            a[2] = uE[(r0    )*132 + ks*8 + kc + 4];
            a[3] = uE[(r0 + 8)*132 + ks*8 + kc + 4];
            #pragma unroll
            for (int nt = 0; nt < 8; nt++) {
                uint32_t bfr[2];
                int n0 = nt*8 + (lid >> 2);
                bfr[0] = uW[n0*132 + ks*8 + kc];
                bfr[1] = uW[n0*132 + ks*8 + kc + 4];
                mma_tf32(acc[nt], a, bfr);
            }
        }

        #pragma unroll
        for (int q = 0; q < 4; q++) {
            int row = 16*wid + (lid >> 2) + ((q >> 1) * 8);
            int h   = (lid & 3)*2 + (q & 1);
            float m = sMask[row];
            float vin  = sigmoidf_(acc[0][q] + sBias[h]      + m) * (acc[1][q] + sBias[8  + h]);
            float vout = sigmoidf_(acc[2][q] + sBias[16 + h] + m) * (acc[3][q] + sBias[24 + h]);
            float ein  = sigmoidf_(acc[4][q] + sBias[32 + h] + m) * (acc[5][q] + sBias[40 + h]);
            float eout = sigmoidf_(acc[6][q] + sBias[48 + h] + m) * (acc[7][q] + sBias[56 + h]);
            sOut[(0*8 + h)*132 + row] = f2tf32(vin);
            sOut[(1*8 + h)*132 + row] = f2tf32(vout);
            sOut[(2*8 + h)*132 + row] = f2tf32(ein);
            sOut[(3*8 + h)*132 + row] = f2tf32(eout);
        }
        __syncthreads();

        {
            int seg = t >> 3;
            int sub = t & 7;
            int tensor = seg >> 3, h = seg & 7;
            float* dst = g_P + ((long)(tensor*16 + b*8 + h)*NN) + (long)x*Nn + y0 + sub*16;
            const float* src = sOut + seg*132 + sub*16;
            #pragma unroll
            for (int q = 0; q < 4; q++)
                *(float4*)(dst + q*4) = *(const float4*)(src + q*4);
        }
        __syncthreads();
    }
}

// ---------------------------------------------------------------------------
// K2: tf32 GEMM, CTA tile 128x128, K-chunk 32, cp.async double-buffered.
// OUTM=false: A/B row-major [i][k]/[j][k], stride 36.
// OUTM=true:  A/B native k-major [k][i]/[k][j], staged [k][*] with stride 136
//             (136 mod 32 = 8 -> transposed LDS fragment reads conflict-free).
// ---------------------------------------------------------------------------
#define K2_STRF   36
#define K2_STRT   136
#define K2_TILEF  4608               // floats per tile buffer (max of modes)
#define K2_BUFF   (2*K2_TILEF)
#define K2_SMEMB  (2*K2_BUFF*4)      // 73728 B

template<bool OUTM>
__global__ __launch_bounds__(256, 2) void k2_mma(float* __restrict__ Va)
{
    extern __shared__ float sm2[];
    const uint32_t sb2 = smem_u32(sm2);
    const int t = threadIdx.x;
    const int wid = t >> 5, lid = t & 31;
    const int warp_m = wid >> 2;
    const int warp_n = wid & 3;

    const int z = blockIdx.z;
    const float* A;
    const float* B;
    float* C;
    if (!OUTM) {
        A = g_P + (long)(2*16 + z)*NN;      // E_in [i][k]
        B = g_P + (long)z*NN;               // V_in [j][k]
        C = Va + (long)((z >> 3)*16 + (z & 7))*NN;
    } else {
        A = g_P + (long)(3*16 + z)*NN;      // E_out [k][i]
        B = g_P + (long)(1*16 + z)*NN;      // V_out [k][j]
        C = Va + (long)((z >> 3)*16 + 8 + (z & 7))*NN;
    }
    const int i0 = blockIdx.y * 128;
    const int j0 = blockIdx.x * 128;

    const int r0k = lid >> 2;
    const int kc4 = lid & 3;

    float acc[4][4][4];
    #pragma unroll
    for (int mt = 0; mt < 4; mt++)
        #pragma unroll
        for (int nt = 0; nt < 4; nt++)
            #pragma unroll
            for (int q = 0; q < 4; q++) acc[mt][nt][q] = 0.f;

    #define K2_STAGE(kc, buf) do { \
        int _k0 = (kc) * 32; \
        if (!OUTM) { \
            _Pragma("unroll") \
            for (int it = 0; it < 8; it++) { \
                int idx = it*256 + t; \
                int half = idx >> 10; \
                int r = (idx >> 3) & 127; \
                int c = idx & 7; \
                const float* src = (half ? B + (long)(j0 + r)*Nn : A + (long)(i0 + r)*Nn) + _k0 + c*4; \
                uint32_t dst = sb2 + (uint32_t)(((buf)*K2_BUFF + half*K2_TILEF + r*K2_STRF + c*4)*4); \
                cpasync16(dst, src); \
            } \
        } else { \
            _Pragma("unroll") \
            for (int it = 0; it < 8; it++) { \
                int idx = it*256 + t; \
                int half = idx >> 10; \
                int kk = (idx >> 5) & 31; \
                int c = idx & 31; \
                const float* src = (half ? B + (long)(_k0 + kk)*Nn + j0 : A + (long)(_k0 + kk)*Nn + i0) + c*4; \
                uint32_t dst = sb2 + (uint32_t)(((buf)*K2_BUFF + half*K2_TILEF + kk*K2_STRT + c*4)*4); \
                cpasync16(dst, src); \
            } \
        } \
        CP_COMMIT(); \
    } while (0)

    K2_STAGE(0, 0);

    for (int kc = 0; kc < 16; kc++) {
        if (kc < 15) { K2_STAGE(kc + 1, (kc + 1) & 1); CP_WAIT1(); }
        else         { CP_WAIT0(); }
        __syncthreads();

        const uint32_t* uA = (const uint32_t*)(sm2 + (kc & 1)*K2_BUFF);
        const uint32_t* uB = uA + K2_TILEF;

        #pragma unroll
        for (int ks = 0; ks < 4; ks++) {
            uint32_t a[4][4];
            #pragma unroll
            for (int mt = 0; mt < 4; mt++) {
                int r0 = warp_m*64 + mt*16 + r0k;
                if (!OUTM) {
                    a[mt][0] = uA[(r0    )*K2_STRF + ks*8 + kc4];
                    a[mt][1] = uA[(r0 + 8)*K2_STRF + ks*8 + kc4];
                    a[mt][2] = uA[(r0    )*K2_STRF + ks*8 + kc4 + 4];
                    a[mt][3] = uA[(r0 + 8)*K2_STRF + ks*8 + kc4 + 4];
                } else {
                    int kk = ks*8 + kc4;
                    a[mt][0] = uA[(kk    )*K2_STRT + r0    ];
                    a[mt][1] = uA[(kk    )*K2_STRT + r0 + 8];
                    a[mt][2] = uA[(kk + 4)*K2_STRT + r0    ];
                    a[mt][3] = uA[(kk + 4)*K2_STRT + r0 + 8];
                }
            }
            #pragma unroll
            for (int nt = 0; nt < 4; nt++) {
                uint32_t bfr[2];
                int n0 = warp_n*32 + nt*8 + r0k;
                if (!OUTM) {
                    bfr[0] = uB[n0*K2_STRF + ks*8 + kc4];
                    bfr[1] = uB[n0*K2_STRF + ks*8 + kc4 + 4];
                } else {
                    int kk = ks*8 + kc4;
                    bfr[0] = uB[(kk    )*K2_STRT + n0];
                    bfr[1] = uB[(kk + 4)*K2_STRT + n0];
                }
                #pragma unroll
                for (int mt = 0; mt < 4; mt++)
                    mma_tf32(acc[mt][nt], a[mt], bfr);
            }
        }
        __syncthreads();
    }

    const int rbase = i0 + warp_m*64 + (lid >> 2);
    const int cbase = j0 + warp_n*32 + (lid & 3)*2;
    #pragma unroll
    for (int mt = 0; mt < 4; mt++)
        #pragma unroll
        for (int nt = 0; nt < 4; nt++) {
            int row = rbase + mt*16;
            int col = cbase + nt*8;
            *(float2*)(C + (long)row*Nn + col)     = make_float2(acc[mt][nt][0], acc[mt][nt][1]);
            *(float2*)(C + (long)(row+8)*Nn + col) = make_float2(acc[mt][nt][2], acc[mt][nt][3]);
        }
}

// ---------------------------------------------------------------------------
// K3: O = Va @ Wo + bo ; out = sigmoid(O[:128]) * O[128:].
// Va staged raw via cp.async into [16 s][520] (520 mod 32 = 8 -> transposed
// fragment LDS conflict-free); tf32 rounding applied on hoisted A registers.
// ---------------------------------------------------------------------------
#define K3_STRV   520
#define K3_OFF_VA 0              // 16*520*4 = 33280
#define K3_OFF_WO 33280          // 256*20*4 = 20480
#define K3_OFF_BO 53760          // 1024
#define K3_SMEM   54784

__global__ __launch_bounds__(256, 2) void k3_outproj(
    const float* __restrict__ bo,
    float* __restrict__ out)
{
    extern __shared__ char smraw[];
    float* sVa = (float*)(smraw + K3_OFF_VA);   // [16][520]
    float* sWo = (float*)(smraw + K3_OFF_WO);   // [256][20]
    float* sBo = (float*)(smraw + K3_OFF_BO);

    const int t   = threadIdx.x;
    const int wid = t >> 5, lid = t & 31;
    const int i = blockIdx.x;
    const int b = blockIdx.y;
    const uint32_t sbVa = smem_u32(sVa);

    // cp.async staging: 16 s-rows x 2048B, raw fp32.
    #pragma unroll
    for (int it = 0; it < 8; it++) {
        int idx = it*256 + t;
        int s = idx >> 7;           // 0..15
        int c = idx & 127;          // 16B chunk -> j = c*4
        cpasync16(sbVa + (uint32_t)((s*K3_STRV + c*4)*4),
                  g_Va + (long)(b*16 + s)*NN + (long)i*Nn + c*4);
    }
    CP_COMMIT();

    if (t < 256) sBo[t] = bo[t];
    for (int idx = t; idx < 4096; idx += 256) {
        int n = idx >> 4, s = idx & 15;
        sWo[n*20 + s] = g_WoT[idx];
    }

    CP_WAIT0();
    __syncthreads();

    const uint32_t* uWo = (const uint32_t*)sWo;
    const int rk = lid >> 2;
    const int kc = lid & 3;

    // A fragments: rows = j (4 m-tiles x 16), cols = s (2 k-steps x 8).
    // Loaded transposed from [s][520] and tf32-rounded in registers
    // (same rna on same values as the old pre-rounding pass).
    uint32_t a[4][2][4];
    #pragma unroll
    for (int mt = 0; mt < 4; mt++) {
        int r0 = wid*64 + mt*16 + rk;
        #pragma unroll
        for (int ks = 0; ks < 2; ks++) {
            int s0 = ks*8 + kc;
            a[mt][ks][0] = __float_as_uint(f2tf32(sVa[(s0    )*K3_STRV + r0    ]));
            a[mt][ks][1] = __float_as_uint(f2tf32(sVa[(s0    )*K3_STRV + r0 + 8]));
            a[mt][ks][2] = __float_as_uint(f2tf32(sVa[(s0 + 4)*K3_STRV + r0    ]));
            a[mt][ks][3] = __float_as_uint(f2tf32(sVa[(s0 + 4)*K3_STRV + r0 + 8]));
        }
    }

    float* obase = out + ((long)(b*Nn + i)*Nn) * 128;

    #pragma unroll 4
    for (int cg = 0; cg < 16; cg++) {
        uint32_t bg[2][2], bl[2][2];
        #pragma unroll
        for (int ks = 0; ks < 2; ks++) {
            int ng = cg*8 + rk;
            bg[ks][0] = uWo[(ng      )*20 + ks*8 + kc];
            bg[ks][1] = uWo[(ng      )*20 + ks*8 + kc + 4];
            bl[ks][0] = uWo[(ng + 128)*20 + ks*8 + kc];
            bl[ks][1] = uWo[(ng + 128)*20 + ks*8 + kc + 4];
        }
        float ag[4][4], al[4][4];
        #pragma unroll
        for (int mt = 0; mt < 4; mt++)
            #pragma unroll
            for (int q = 0; q < 4; q++) { ag[mt][q] = 0.f; al[mt][q] = 0.f; }
        #pragma unroll
        for (int ks = 0; ks < 2; ks++)
            #pragma unroll
            for (int mt = 0; mt < 4; mt++) {
                mma_tf32(ag[mt], a[mt][ks], bg[ks]);
                mma_tf32(al[mt], a[mt][ks], bl[ks]);
            }
        int c0 = cg*8 + (lid & 3)*2;
        float bg0 = sBo[c0], bg1 = sBo[c0+1], bl0 = sBo[c0+128], bl1 = sBo[c0+129];
        #pragma unroll
        for (int mt = 0; mt < 4; mt++) {
            int r = wid*64 + mt*16 + (lid >> 2);
            *(float2*)(obase + (long)r*128 + c0) = make_float2(
                sigmoidf_(ag[mt][0] + bg0) * (al[mt][0] + bl0),
                sigmoidf_(ag[mt][1] + bg1) * (al[mt][1] + bl1));
            *(float2*)(obase + (long)(r+8)*128 + c0) = make_float2(
                sigmoidf_(ag[mt][2] + bg0) * (al[mt][2] + bl0),
                sigmoidf_(ag[mt][3] + bg1) * (al[mt][3] + bl1));
        }
    }
}

// ---------------------------------------------------------------------------
extern "C" void kernel_launch(void* const* d_in, const int* in_sizes, int n_in,
                              void* d_out, int out_size)
{
    const float* e    = (const float*)d_in[0];
    const float* mask = (const float*)d_in[1];
    const float* lnw  = (const float*)d_in[2];
    const float* lnb  = (const float*)d_in[3];
    const float* Wv   = (const float*)d_in[4];
    const float* bv   = (const float*)d_in[5];
    const float* We   = (const float*)d_in[6];
    const float* be   = (const float*)d_in[7];
    const float* Wo   = (const float*)d_in[8];
    const float* bo   = (const float*)d_in[9];
    float* out = (float*)d_out;

    static float* s_va = nullptr;
    static int smcount = 0;
    if (!s_va) {
        cudaGetSymbolAddress((void**)&s_va, g_Va);
        cudaDeviceGetAttribute(&smcount, cudaDevAttrMultiProcessorCount, 0);
        if (smcount <= 0) smcount = 148;
        cudaFuncSetAttribute(k1_ln_proj_gate,
                             cudaFuncAttributeMaxDynamicSharedMemorySize, K1_SMEM);
        cudaFuncSetAttribute(k2_mma<false>,
                             cudaFuncAttributeMaxDynamicSharedMemorySize, K2_SMEMB);
        cudaFuncSetAttribute(k2_mma<true>,
                             cudaFuncAttributeMaxDynamicSharedMemorySize, K2_SMEMB);
        cudaFuncSetAttribute(k3_outproj,
                             cudaFuncAttributeMaxDynamicSharedMemorySize, K3_SMEM);
    }

    k0_prep<<<1, 256>>>(Wv, We, Wo);

    k1_ln_proj_gate<<<smcount, 256, K1_SMEM>>>(e, mask, lnw, lnb, bv, be);

    dim3 g2(4, 4, 16);
    k2_mma<false><<<g2, 256, K2_SMEMB>>>(s_va);
    k2_mma<true ><<<g2, 256, K2_SMEMB>>>(s_va);

    dim3 g3(Nn, Bb);
    k3_outproj<<<g3, 256, K3_SMEM>>>(bo, out);
}